// round 1
// baseline (speedup 1.0000x reference)
#include <cuda_runtime.h>
#include <cstdint>
#include <math.h>

// ---------------- problem constants ----------------
#define B_      4
#define P_      4096
#define FULL_   4096
#define SLICE_  512
#define EDIM_   1024
#define SLS_    1024          // slice start
#define FPMIN_  0.1875f
#define FPMAX_  0.4375f

// ---------------- scratch (no allocs allowed) ----------------
__device__ float g_my[(size_t)B_ * P_ * SLICE_];   // scaled gathered slice, M x 512 (worst case N=P)
__device__ float g_Wg1T[512 * 128];                // W_g1 transposed: [k][i]
__device__ int   g_idx[P_];                        // compacted token indices
__device__ float g_dirs[5 * EDIM_];                // normalized pentachoron

// ---------------- f32x2 helpers ----------------
__device__ __forceinline__ void fma2(unsigned long long &d, unsigned long long a, unsigned long long b) {
    asm("fma.rn.f32x2 %0, %1, %2, %0;" : "+l"(d) : "l"(a), "l"(b));
}
__device__ __forceinline__ unsigned long long pk2(float lo, float hi) {
    unsigned long long r; asm("mov.b64 %0, {%1, %2};" : "=l"(r) : "f"(lo), "f"(hi)); return r;
}
__device__ __forceinline__ void upk2(unsigned long long v, float &lo, float &hi) {
    asm("mov.b64 {%0, %1}, %2;" : "=f"(lo), "=f"(hi) : "l"(v));
}

// =====================================================================
// K1: compaction (sorted), W_g1 transpose, dirs normalization. 1 block.
// =====================================================================
__global__ void k_prep(const float* __restrict__ fps,
                       const float* __restrict__ W_g1,
                       const float* __restrict__ penta)
{
    __shared__ int cnt_s[256];
    int t = threadIdx.x;  // 256 threads

    // ---- compaction: each thread owns 16 consecutive fingerprints ----
    int base = t * 16;
    unsigned mask16 = 0;
    int c = 0;
    #pragma unroll
    for (int i = 0; i < 16; ++i) {
        float f = fps[base + i];
        bool m = (f >= FPMIN_) && (f < FPMAX_);
        mask16 |= (m ? 1u : 0u) << i;
        c += m ? 1 : 0;
    }
    cnt_s[t] = c;
    __syncthreads();
    // Hillis-Steele inclusive scan over 256 counts
    for (int d = 1; d < 256; d <<= 1) {
        int x = (t >= d) ? cnt_s[t - d] : 0;
        __syncthreads();
        cnt_s[t] += x;
        __syncthreads();
    }
    int off = cnt_s[t] - c;   // exclusive prefix
    #pragma unroll
    for (int i = 0; i < 16; ++i)
        if (mask16 & (1u << i)) g_idx[off++] = base + i;

    // ---- W_g1 transpose: g_Wg1T[k*128 + i] = W_g1[i*512 + k] ----
    for (int idx = t; idx < 512 * 128; idx += 256) {
        int k = idx >> 7, i = idx & 127;
        g_Wg1T[idx] = W_g1[i * 512 + k];
    }

    // ---- dirs: 5 warps, one direction each ----
    if (t < 160) {
        int w = t >> 5, lane = t & 31;
        float s = 0.f;
        #pragma unroll
        for (int kk = 0; kk < 32; ++kk) {
            float x = penta[w * EDIM_ + kk * 32 + lane];
            s += x * x;
        }
        #pragma unroll
        for (int o = 16; o >= 1; o >>= 1) s += __shfl_xor_sync(0xffffffffu, s, o);
        float inv = rsqrtf(s);
        #pragma unroll
        for (int kk = 0; kk < 32; ++kk) {
            int id = w * EDIM_ + kk * 32 + lane;
            g_dirs[id] = penta[id] * inv;
        }
    }
}

// =====================================================================
// K2: gather + gate MLP (exact GELU) + scale -> g_my.  8 rows/block, 128 thr.
// =====================================================================
#define GROWS 8
__global__ void k_gate(const float* __restrict__ tokens,
                       const float* __restrict__ b_g1,
                       const float* __restrict__ W_g2,
                       const float* __restrict__ b_g2,
                       const float* __restrict__ alphap,
                       int N, int M)
{
    __shared__ __align__(16) float my_s[GROWS][512];
    __shared__ float hw_s[GROWS][136];
    __shared__ float scale_s[GROWS];
    int t = threadIdx.x;   // 128
    int r0 = blockIdx.x * GROWS;

    // gather 8 rows of the slice (512 f32 each)
    #pragma unroll
    for (int r = 0; r < GROWS; ++r) {
        int gr = r0 + r;
        float4* dst = (float4*)&my_s[r][0];
        if (gr < M) {
            int b = gr / N, j = gr - b * N;
            int p = g_idx[j];
            const float4* src = (const float4*)(tokens + ((size_t)b * P_ + p) * FULL_ + SLS_);
            dst[t] = src[t];
        } else {
            dst[t] = make_float4(0.f, 0.f, 0.f, 0.f);
        }
    }
    __syncthreads();

    // h[i] for i = t, all 8 rows
    float acc[GROWS];
    #pragma unroll
    for (int r = 0; r < GROWS; ++r) acc[r] = 0.f;
    #pragma unroll 4
    for (int k = 0; k < 512; ++k) {
        float w = g_Wg1T[k * 128 + t];
        #pragma unroll
        for (int r = 0; r < GROWS; ++r) acc[r] += w * my_s[r][k];
    }
    float bb = b_g1[t];
    float w2 = W_g2[t];
    #pragma unroll
    for (int r = 0; r < GROWS; ++r) {
        float x = acc[r] + bb;
        float h = 0.5f * x * (1.f + erff(x * 0.70710678118654752f));  // exact gelu
        hw_s[r][t] = h * w2;
    }
    __syncthreads();

    // per-row reduce of 128 values -> gate -> scale
    {
        int r = t >> 4, l = t & 15;
        float s = 0.f;
        #pragma unroll
        for (int q = 0; q < 8; ++q) s += hw_s[r][l + 16 * q];
        #pragma unroll
        for (int o = 8; o >= 1; o >>= 1) s += __shfl_xor_sync(0xffffffffu, s, o, 16);
        if (l == 0) {
            float gate = 1.f / (1.f + expf(-(s + b_g2[0])));
            float aw   = 1.f / (1.f + expf(-alphap[0]));
            scale_s[r] = gate * aw + (1.f - aw);
        }
    }
    __syncthreads();

    // scale and write out
    #pragma unroll
    for (int r = 0; r < GROWS; ++r) {
        int gr = r0 + r;
        if (gr < M) {
            float sc = scale_s[r];
            float4 v = ((float4*)&my_s[r][0])[t];
            v.x *= sc; v.y *= sc; v.z *= sc; v.w *= sc;
            ((float4*)(g_my + (size_t)gr * 512))[t] = v;
        }
    }
}

// =====================================================================
// K3: GEMM  C[M,3072] = g_my[M,512] @ [Wq;Wk;Wv]^T, written straight into
//     d_out (Q | K | V regions).  128x128x16 tiles, 256 thr, f32x2 FMA.
// =====================================================================
__global__ void __launch_bounds__(256)
k_gemm(const float* __restrict__ Wq, const float* __restrict__ Wk,
       const float* __restrict__ Wv, float* __restrict__ out, int M)
{
    __shared__ __align__(16) float As[16][128];
    __shared__ __align__(16) float Bs[16][128];

    int tid = threadIdx.x;
    int m0 = blockIdx.y * 128;
    int n0 = blockIdx.x * 128;   // 0..2944
    int sel  = n0 >> 10;         // which matrix
    int ncol = n0 & 1023;
    const float* W = (sel == 0) ? Wq : (sel == 1 ? Wk : Wv);

    int tm = tid >> 4;     // 0..15
    int tn = tid & 15;     // 0..15

    unsigned long long acc[8][4];
    #pragma unroll
    for (int i = 0; i < 8; ++i)
        #pragma unroll
        for (int j = 0; j < 4; ++j) acc[i][j] = 0ull;

    for (int k0 = 0; k0 < 512; k0 += 16) {
        // load A tile (128 rows x 16 k), transposed to As[k][m]
        #pragma unroll
        for (int l = 0; l < 2; ++l) {
            int f = tid + l * 256;
            int row = f >> 2, kq = (f & 3) * 4;
            float4 v = make_float4(0.f, 0.f, 0.f, 0.f);
            int gr = m0 + row;
            if (gr < M) v = *(const float4*)(g_my + (size_t)gr * 512 + k0 + kq);
            As[kq + 0][row] = v.x; As[kq + 1][row] = v.y;
            As[kq + 2][row] = v.z; As[kq + 3][row] = v.w;
        }
        // load B tile (128 cols x 16 k), transposed to Bs[k][n]
        #pragma unroll
        for (int l = 0; l < 2; ++l) {
            int f = tid + l * 256;
            int row = f >> 2, kq = (f & 3) * 4;
            float4 v = *(const float4*)(W + (size_t)(ncol + row) * 512 + k0 + kq);
            Bs[kq + 0][row] = v.x; Bs[kq + 1][row] = v.y;
            Bs[kq + 2][row] = v.z; Bs[kq + 3][row] = v.w;
        }
        __syncthreads();

        #pragma unroll 2
        for (int kk = 0; kk < 16; ++kk) {
            const float4* Ar = (const float4*)&As[kk][0];
            float4 a0 = Ar[tm * 2], a1 = Ar[tm * 2 + 1];
            const unsigned long long* Bq = (const unsigned long long*)&Bs[kk][0];
            unsigned long long b[4];
            #pragma unroll
            for (int j = 0; j < 4; ++j) b[j] = Bq[tn * 4 + j];
            float a[8] = {a0.x, a0.y, a0.z, a0.w, a1.x, a1.y, a1.z, a1.w};
            unsigned long long asp[8];
            #pragma unroll
            for (int i = 0; i < 8; ++i) asp[i] = pk2(a[i], a[i]);
            #pragma unroll
            for (int i = 0; i < 8; ++i)
                #pragma unroll
                for (int j = 0; j < 4; ++j) fma2(acc[i][j], asp[i], b[j]);
        }
        __syncthreads();
    }

    // epilogue: write into d_out, Q|K|V each [B*N, 1024] contiguous
    size_t matbase = (size_t)sel * M * EDIM_;
    #pragma unroll
    for (int i = 0; i < 8; ++i) {
        int gr = m0 + tm * 8 + i;
        if (gr >= M) break;
        float* orow = out + matbase + (size_t)gr * EDIM_ + ncol + tn * 8;
        float c0, c1, c2, c3;
        upk2(acc[i][0], c0, c1); upk2(acc[i][1], c2, c3);
        *(float4*)(orow + 0) = make_float4(c0, c1, c2, c3);
        upk2(acc[i][2], c0, c1); upk2(acc[i][3], c2, c3);
        *(float4*)(orow + 4) = make_float4(c0, c1, c2, c3);
    }
}

// =====================================================================
// K4: pentachoron projections. One warp per QKV row, 8 rows per block.
// =====================================================================
__global__ void k_proj(float* __restrict__ out, int N)
{
    __shared__ float dirs_s[5 * EDIM_];
    int t = threadIdx.x;  // 256
    for (int i = t; i < 5 * EDIM_; i += 256) dirs_s[i] = g_dirs[i];
    __syncthreads();

    int w = t >> 5, lane = t & 31;
    long long g = (long long)blockIdx.x * 8 + w;
    long long R = 12LL * N;
    if (g >= R) return;

    const float* row = out + g * EDIM_;
    float acc[5] = {0.f, 0.f, 0.f, 0.f, 0.f};
    #pragma unroll
    for (int kk = 0; kk < 32; ++kk) {
        float x = row[kk * 32 + lane];
        #pragma unroll
        for (int v = 0; v < 5; ++v) acc[v] += x * dirs_s[v * EDIM_ + kk * 32 + lane];
    }
    #pragma unroll
    for (int v = 0; v < 5; ++v)
        #pragma unroll
        for (int o = 16; o >= 1; o >>= 1)
            acc[v] += __shfl_xor_sync(0xffffffffu, acc[v], o);

    if (lane == 0) {
        long long fourN = 4LL * N;
        int sel = (int)(g / fourN);
        long long r = g - (long long)sel * fourN;
        size_t base = (size_t)12 * N * EDIM_ + (size_t)sel * 5 * fourN;
        #pragma unroll
        for (int v = 0; v < 5; ++v)
            out[base + (size_t)v * fourN + r] = acc[v];
    }
}

// =====================================================================
extern "C" void kernel_launch(void* const* d_in, const int* in_sizes, int n_in,
                              void* d_out, int out_size)
{
    const float* tokens = (const float*)d_in[0];
    const float* fps    = (const float*)d_in[1];
    const float* W_g1   = (const float*)d_in[2];
    const float* b_g1   = (const float*)d_in[3];
    const float* W_g2   = (const float*)d_in[4];
    const float* b_g2   = (const float*)d_in[5];
    const float* alpha  = (const float*)d_in[6];
    const float* Wq     = (const float*)d_in[7];
    const float* Wk     = (const float*)d_in[8];
    const float* Wv     = (const float*)d_in[9];
    const float* penta  = (const float*)d_in[10];

    // out = Q|K|V ([B,N,1024] each) + Qp|Kp|Vp ([5,B,N] each): 12348 floats / token
    int N = out_size / 12348;
    if (N <= 0) return;
    int M = 4 * N;
    float* out = (float*)d_out;

    k_prep<<<1, 256>>>(fps, W_g1, penta);
    k_gate<<<(M + GROWS - 1) / GROWS, 128>>>(tokens, b_g1, W_g2, b_g2, alpha, N, M);
    dim3 g3(24, (M + 127) / 128);
    k_gemm<<<g3, 256>>>(Wq, Wk, Wv, out, M);
    k_proj<<<(int)((12LL * N + 7) / 8), 256>>>(out, N);
}

// round 3
// speedup vs baseline: 1.6896x; 1.6896x over previous
#include <cuda_runtime.h>
#include <cuda_bf16.h>
#include <cstdint>
#include <math.h>

// ---------------- problem constants ----------------
#define B_      4
#define P_      4096
#define FULL_   4096
#define SLICE_  512
#define EDIM_   1024
#define SLS_    1024          // slice start
#define FPMIN_  0.1875f
#define FPMAX_  0.4375f
#define KCAT    1536          // concatenated K = 3*512 (hi|hi|lo vs hi|lo|hi)

// ---------------- scratch (no allocs allowed) ----------------
__device__ __align__(16) __nv_bfloat16 g_A2[(size_t)B_ * P_ * KCAT];  // [hi|hi|lo] rows (zero padded)
__device__ __align__(16) __nv_bfloat16 g_B2[(size_t)3 * EDIM_ * KCAT];// [hi|lo|hi] rows for Wq|Wk|Wv
__device__ float g_Wg1T[512 * 128];
__device__ int   g_idx[P_];
__device__ float g_dirs[5 * EDIM_];

// ---------------- PTX helpers (sm_103-base-safe only) ----------------
__device__ __forceinline__ uint32_t smem_u32(const void* p) {
    uint32_t a; asm("{ .reg .u64 t; cvta.to.shared.u64 t, %1; cvt.u32.u64 %0, t; }" : "=r"(a) : "l"(p)); return a;
}
#define CP_ASYNC16(dst, src) \
    asm volatile("cp.async.cg.shared.global [%0], [%1], 16;" :: "r"(dst), "l"(src))
#define CP_COMMIT() asm volatile("cp.async.commit_group;" ::: "memory")
#define CP_WAIT1()  asm volatile("cp.async.wait_group 1;" ::: "memory")

#define LDSM4(r0, r1, r2, r3, a) \
    asm volatile("ldmatrix.sync.aligned.m8n8.x4.shared.b16 {%0,%1,%2,%3}, [%4];" \
        : "=r"(r0), "=r"(r1), "=r"(r2), "=r"(r3) : "r"(a))

#define MMA16816(c, a, b0, b1) \
    asm volatile("mma.sync.aligned.m16n8k16.row.col.f32.bf16.bf16.f32 " \
        "{%0,%1,%2,%3},{%4,%5,%6,%7},{%8,%9},{%0,%1,%2,%3};" \
        : "+f"((c)[0]), "+f"((c)[1]), "+f"((c)[2]), "+f"((c)[3]) \
        : "r"((a)[0]), "r"((a)[1]), "r"((a)[2]), "r"((a)[3]), "r"(b0), "r"(b1))

// =====================================================================
// K1: compaction (sorted), W_g1 transpose, dirs normalization. 1 block.
// =====================================================================
__global__ void k_prep(const float* __restrict__ fps,
                       const float* __restrict__ W_g1,
                       const float* __restrict__ penta)
{
    __shared__ int cnt_s[256];
    int t = threadIdx.x;  // 256 threads

    int base = t * 16;
    unsigned mask16 = 0;
    int c = 0;
    #pragma unroll
    for (int i = 0; i < 16; ++i) {
        float f = fps[base + i];
        bool m = (f >= FPMIN_) && (f < FPMAX_);
        mask16 |= (m ? 1u : 0u) << i;
        c += m ? 1 : 0;
    }
    cnt_s[t] = c;
    __syncthreads();
    for (int d = 1; d < 256; d <<= 1) {
        int x = (t >= d) ? cnt_s[t - d] : 0;
        __syncthreads();
        cnt_s[t] += x;
        __syncthreads();
    }
    int off = cnt_s[t] - c;
    #pragma unroll
    for (int i = 0; i < 16; ++i)
        if (mask16 & (1u << i)) g_idx[off++] = base + i;

    for (int idx = t; idx < 512 * 128; idx += 256) {
        int k = idx >> 7, i = idx & 127;
        g_Wg1T[idx] = W_g1[i * 512 + k];
    }

    if (t < 160) {
        int w = t >> 5, lane = t & 31;
        float s = 0.f;
        #pragma unroll
        for (int kk = 0; kk < 32; ++kk) {
            float x = penta[w * EDIM_ + kk * 32 + lane];
            s += x * x;
        }
        #pragma unroll
        for (int o = 16; o >= 1; o >>= 1) s += __shfl_xor_sync(0xffffffffu, s, o);
        float inv = rsqrtf(s);
        #pragma unroll
        for (int kk = 0; kk < 32; ++kk) {
            int id = w * EDIM_ + kk * 32 + lane;
            g_dirs[id] = penta[id] * inv;
        }
    }
}

// =====================================================================
// K1b: build B'' = [hi | lo | hi] bf16 rows from Wq|Wk|Wv
// =====================================================================
__global__ void k_prepW(const float* __restrict__ Wq,
                        const float* __restrict__ Wk,
                        const float* __restrict__ Wv)
{
    int id = blockIdx.x * 256 + threadIdx.x;   // each handles 4 k of one row
    int n  = id >> 7;                          // 0..3071
    int k4 = (id & 127) * 4;
    const float* W = (n < 1024) ? Wq : (n < 2048 ? Wk : Wv);
    int nn = n & 1023;
    float4 v = *(const float4*)(W + (size_t)nn * 512 + k4);
    __nv_bfloat16 h0 = __float2bfloat16(v.x), h1 = __float2bfloat16(v.y);
    __nv_bfloat16 h2 = __float2bfloat16(v.z), h3 = __float2bfloat16(v.w);
    __nv_bfloat16 l0 = __float2bfloat16(v.x - __bfloat162float(h0));
    __nv_bfloat16 l1 = __float2bfloat16(v.y - __bfloat162float(h1));
    __nv_bfloat16 l2 = __float2bfloat16(v.z - __bfloat162float(h2));
    __nv_bfloat16 l3 = __float2bfloat16(v.w - __bfloat162float(h3));
    size_t base = (size_t)n * KCAT;
    __nv_bfloat162* d0 = (__nv_bfloat162*)(g_B2 + base + k4);
    __nv_bfloat162* d1 = (__nv_bfloat162*)(g_B2 + base + 512 + k4);
    __nv_bfloat162* d2 = (__nv_bfloat162*)(g_B2 + base + 1024 + k4);
    d0[0] = __nv_bfloat162(h0, h1); d0[1] = __nv_bfloat162(h2, h3);
    d1[0] = __nv_bfloat162(l0, l1); d1[1] = __nv_bfloat162(l2, l3);
    d2[0] = __nv_bfloat162(h0, h1); d2[1] = __nv_bfloat162(h2, h3);
}

// =====================================================================
// K2: gather + gate MLP (exact GELU) + scale -> g_A2 [hi|hi|lo] bf16
// =====================================================================
#define GROWS 8
__global__ void k_gate(const float* __restrict__ tokens,
                       const float* __restrict__ b_g1,
                       const float* __restrict__ W_g2,
                       const float* __restrict__ b_g2,
                       const float* __restrict__ alphap,
                       int N, int M)
{
    __shared__ __align__(16) float my_s[GROWS][512];
    __shared__ float hw_s[GROWS][136];
    __shared__ float scale_s[GROWS];
    int t = threadIdx.x;   // 128
    int r0 = blockIdx.x * GROWS;

    #pragma unroll
    for (int r = 0; r < GROWS; ++r) {
        int gr = r0 + r;
        float4* dst = (float4*)&my_s[r][0];
        if (gr < M) {
            int b = gr / N, j = gr - b * N;
            int p = g_idx[j];
            const float4* src = (const float4*)(tokens + ((size_t)b * P_ + p) * FULL_ + SLS_);
            dst[t] = src[t];
        } else {
            dst[t] = make_float4(0.f, 0.f, 0.f, 0.f);
        }
    }
    __syncthreads();

    float acc[GROWS];
    #pragma unroll
    for (int r = 0; r < GROWS; ++r) acc[r] = 0.f;
    #pragma unroll 4
    for (int k = 0; k < 512; ++k) {
        float w = g_Wg1T[k * 128 + t];
        #pragma unroll
        for (int r = 0; r < GROWS; ++r) acc[r] += w * my_s[r][k];
    }
    float bb = b_g1[t];
    float w2 = W_g2[t];
    #pragma unroll
    for (int r = 0; r < GROWS; ++r) {
        float x = acc[r] + bb;
        float h = 0.5f * x * (1.f + erff(x * 0.70710678118654752f));
        hw_s[r][t] = h * w2;
    }
    __syncthreads();

    {
        int r = t >> 4, l = t & 15;
        float s = 0.f;
        #pragma unroll
        for (int q = 0; q < 8; ++q) s += hw_s[r][l + 16 * q];
        #pragma unroll
        for (int o = 8; o >= 1; o >>= 1) s += __shfl_xor_sync(0xffffffffu, s, o, 16);
        if (l == 0) {
            float gate = 1.f / (1.f + expf(-(s + b_g2[0])));
            float aw   = 1.f / (1.f + expf(-alphap[0]));
            scale_s[r] = gate * aw + (1.f - aw);
        }
    }
    __syncthreads();

    // scale, split to bf16 hi/lo, write A'' = [hi | hi | lo]
    #pragma unroll
    for (int r = 0; r < GROWS; ++r) {
        int gr = r0 + r;
        float sc = scale_s[r];
        float4 v = ((float4*)&my_s[r][0])[t];
        v.x *= sc; v.y *= sc; v.z *= sc; v.w *= sc;
        __nv_bfloat16 h0 = __float2bfloat16(v.x), h1 = __float2bfloat16(v.y);
        __nv_bfloat16 h2 = __float2bfloat16(v.z), h3 = __float2bfloat16(v.w);
        __nv_bfloat16 l0 = __float2bfloat16(v.x - __bfloat162float(h0));
        __nv_bfloat16 l1 = __float2bfloat16(v.y - __bfloat162float(h1));
        __nv_bfloat16 l2 = __float2bfloat16(v.z - __bfloat162float(h2));
        __nv_bfloat16 l3 = __float2bfloat16(v.w - __bfloat162float(h3));
        size_t base = (size_t)gr * KCAT;
        int k4 = t * 4;
        __nv_bfloat162* d0 = (__nv_bfloat162*)(g_A2 + base + k4);
        __nv_bfloat162* d1 = (__nv_bfloat162*)(g_A2 + base + 512 + k4);
        __nv_bfloat162* d2 = (__nv_bfloat162*)(g_A2 + base + 1024 + k4);
        d0[0] = __nv_bfloat162(h0, h1); d0[1] = __nv_bfloat162(h2, h3);
        d1[0] = __nv_bfloat162(h0, h1); d1[1] = __nv_bfloat162(h2, h3);
        d2[0] = __nv_bfloat162(l0, l1); d2[1] = __nv_bfloat162(l2, l3);
    }
}

// =====================================================================
// K3: HMMA (mma.sync bf16) GEMM  C[Mpad,3072] = A''[Mpad,1536] @ B''^T
//     128x128 tile, BK=64, 3-stage cp.async pipeline, padded smem (144B).
// =====================================================================
#define LDA        72                    // padded row stride in bf16 (144 B)
#define TILE_ELEM  (128 * LDA)
#define TILE_B     (TILE_ELEM * 2)       // 18432 bytes
#define STAGE_B2   (2 * TILE_B)
#define NSTAGE     3
#define GEMM_SMEM  (NSTAGE * STAGE_B2)   // 110592 bytes
#define NS         (KCAT / 64)           // 24 k-chunks

__global__ void __launch_bounds__(256, 1)
k_gemm_mma(float* __restrict__ out, int M)
{
    extern __shared__ char smem[];
    const uint32_t sb = smem_u32(smem);
    const int tid = threadIdx.x, lane = tid & 31;
    const int wid = tid >> 5;
    const int wm = wid & 3, wn = wid >> 2;          // 4 x 2 warp grid
    const int m0 = blockIdx.y * 128;
    const int n0 = blockIdx.x * 128;

    const __nv_bfloat16* Ag = g_A2 + (size_t)m0 * KCAT;
    const __nv_bfloat16* Bg = g_B2 + (size_t)n0 * KCAT;

    const int ldRow = tid >> 3, ldCh = (tid & 7) * 8;

    float acc[2][8][4];
    #pragma unroll
    for (int h = 0; h < 2; ++h)
        #pragma unroll
        for (int j = 0; j < 8; ++j)
            #pragma unroll
            for (int q = 0; q < 4; ++q) acc[h][j][q] = 0.f;

    // prologue: stages 0 and 1
    #pragma unroll
    for (int pre = 0; pre < 2; ++pre) {
        uint32_t base = sb + pre * STAGE_B2;
        #pragma unroll
        for (int i = 0; i < 4; ++i) {
            int row = ldRow + i * 32;
            uint32_t doff = (uint32_t)(row * LDA + ldCh) * 2;
            CP_ASYNC16(base + doff, (const void*)(Ag + (size_t)row * KCAT + pre * 64 + ldCh));
            CP_ASYNC16(base + TILE_B + doff, (const void*)(Bg + (size_t)row * KCAT + pre * 64 + ldCh));
        }
        CP_COMMIT();
    }

    #pragma unroll 1
    for (int s = 0; s < NS; ++s) {
        CP_WAIT1();
        __syncthreads();
        if (s + 2 < NS) {
            int b = (s + 2) % NSTAGE;
            uint32_t base = sb + b * STAGE_B2;
            #pragma unroll
            for (int i = 0; i < 4; ++i) {
                int row = ldRow + i * 32;
                uint32_t doff = (uint32_t)(row * LDA + ldCh) * 2;
                CP_ASYNC16(base + doff, (const void*)(Ag + (size_t)row * KCAT + (s + 2) * 64 + ldCh));
                CP_ASYNC16(base + TILE_B + doff, (const void*)(Bg + (size_t)row * KCAT + (s + 2) * 64 + ldCh));
            }
        }
        CP_COMMIT();

        const uint32_t stg = sb + (s % NSTAGE) * STAGE_B2;
        const uint32_t aB = stg + (uint32_t)(wm * 32 * LDA) * 2;
        const uint32_t bB = stg + TILE_B + (uint32_t)(wn * 64 * LDA) * 2;
        const uint32_t aAddr0 = aB + (uint32_t)((lane & 15) * LDA) * 2 + (lane >> 4) * 16;
        const uint32_t bRowOff = (uint32_t)((((lane >> 4) & 1) * 8 + (lane & 7)) * LDA) * 2;
        const uint32_t bChunk = ((lane >> 3) & 1) * 16;

        #pragma unroll
        for (int kk = 0; kk < 4; ++kk) {
            uint32_t a0[4], a1[4];
            LDSM4(a0[0], a0[1], a0[2], a0[3], aAddr0 + kk * 32);
            LDSM4(a1[0], a1[1], a1[2], a1[3], aAddr0 + (uint32_t)(16 * LDA) * 2 + kk * 32);
            #pragma unroll
            for (int p = 0; p < 4; ++p) {
                uint32_t b0, b1, b2, b3;
                uint32_t ba = bB + (uint32_t)(p * 16 * LDA) * 2 + bRowOff + kk * 32 + bChunk;
                LDSM4(b0, b1, b2, b3, ba);
                MMA16816(acc[0][2 * p],     a0, b0, b1);
                MMA16816(acc[0][2 * p + 1], a0, b2, b3);
                MMA16816(acc[1][2 * p],     a1, b0, b1);
                MMA16816(acc[1][2 * p + 1], a1, b2, b3);
            }
        }
        __syncthreads();
    }

    // ---- epilogue ----
    const int sel  = n0 >> 10;
    const int ncolB = (n0 & 1023) + wn * 64;
    float* outM = out + (size_t)sel * M * EDIM_;
    #pragma unroll
    for (int h = 0; h < 2; ++h) {
        int rbase = m0 + wm * 32 + h * 16 + (lane >> 2);
        #pragma unroll
        for (int rr = 0; rr < 2; ++rr) {
            int grow = rbase + rr * 8;
            if (grow < M) {
                float* orow = outM + (size_t)grow * EDIM_ + ncolB + 2 * (lane & 3);
                #pragma unroll
                for (int j = 0; j < 8; ++j) {
                    float2 v = make_float2(acc[h][j][2 * rr], acc[h][j][2 * rr + 1]);
                    *(float2*)(orow + j * 8) = v;
                }
            }
        }
    }
}

// =====================================================================
// K4: pentachoron projections. One warp per QKV row, 8 rows per block.
// =====================================================================
__global__ void k_proj(float* __restrict__ out, int N)
{
    __shared__ float dirs_s[5 * EDIM_];
    int t = threadIdx.x;  // 256
    for (int i = t; i < 5 * EDIM_; i += 256) dirs_s[i] = g_dirs[i];
    __syncthreads();

    int w = t >> 5, lane = t & 31;
    long long g = (long long)blockIdx.x * 8 + w;
    long long R = 12LL * N;
    if (g >= R) return;

    const float* row = out + g * EDIM_;
    float acc[5] = {0.f, 0.f, 0.f, 0.f, 0.f};
    #pragma unroll
    for (int kk = 0; kk < 32; ++kk) {
        float x = row[kk * 32 + lane];
        #pragma unroll
        for (int v = 0; v < 5; ++v) acc[v] += x * dirs_s[v * EDIM_ + kk * 32 + lane];
    }
    #pragma unroll
    for (int v = 0; v < 5; ++v)
        #pragma unroll
        for (int o = 16; o >= 1; o >>= 1)
            acc[v] += __shfl_xor_sync(0xffffffffu, acc[v], o);

    if (lane == 0) {
        long long fourN = 4LL * N;
        int sel = (int)(g / fourN);
        long long r = g - (long long)sel * fourN;
        size_t base = (size_t)12 * N * EDIM_ + (size_t)sel * 5 * fourN;
        #pragma unroll
        for (int v = 0; v < 5; ++v)
            out[base + (size_t)v * fourN + r] = acc[v];
    }
}

// =====================================================================
extern "C" void kernel_launch(void* const* d_in, const int* in_sizes, int n_in,
                              void* d_out, int out_size)
{
    const float* tokens = (const float*)d_in[0];
    const float* fps    = (const float*)d_in[1];
    const float* W_g1   = (const float*)d_in[2];
    const float* b_g1   = (const float*)d_in[3];
    const float* W_g2   = (const float*)d_in[4];
    const float* b_g2   = (const float*)d_in[5];
    const float* alpha  = (const float*)d_in[6];
    const float* Wq     = (const float*)d_in[7];
    const float* Wk     = (const float*)d_in[8];
    const float* Wv     = (const float*)d_in[9];
    const float* penta  = (const float*)d_in[10];

    int N = out_size / 12348;       // per token: 3*1024 QKV + 3*5 projections
    if (N <= 0) return;
    int M = 4 * N;
    int Mpad = (M + 127) & ~127;
    float* out = (float*)d_out;

    cudaFuncSetAttribute(k_gemm_mma, cudaFuncAttributeMaxDynamicSharedMemorySize, GEMM_SMEM);

    k_prep<<<1, 256>>>(fps, W_g1, penta);
    k_prepW<<<1536, 256>>>(Wq, Wk, Wv);
    k_gate<<<Mpad / GROWS, 128>>>(tokens, b_g1, W_g2, b_g2, alpha, N, M);
    dim3 g3(24, Mpad / 128);
    k_gemm_mma<<<g3, 256, GEMM_SMEM>>>(out, M);
    k_proj<<<(int)((12LL * N + 7) / 8), 256>>>(out, N);
}

// round 4
// speedup vs baseline: 3.2021x; 1.8952x over previous
#include <cuda_runtime.h>
#include <cuda_bf16.h>
#include <cstdint>
#include <math.h>

// ---------------- problem constants ----------------
#define B_      4
#define P_      4096
#define FULL_   4096
#define SLICE_  512
#define EDIM_   1024
#define SLS_    1024          // slice start
#define FPMIN_  0.1875f
#define FPMAX_  0.4375f
#define KCAT    1536          // concatenated K = 3*512

// ---------------- scratch (no allocs allowed) ----------------
__device__ __align__(16) __nv_bfloat16 g_A2[(size_t)B_ * P_ * KCAT];   // tokens slice, [hi|hi|lo], UNSCALED
__device__ __align__(16) __nv_bfloat16 g_B2[(size_t)3 * EDIM_ * KCAT]; // Wq|Wk|Wv, [hi|lo|hi]
__device__ __align__(16) __nv_bfloat16 g_W1[(size_t)128 * KCAT];       // W_g1, [hi|lo|hi]
__device__ float g_scale[B_ * P_ + 128];
__device__ int   g_idx[P_];
__device__ __align__(16) float g_dirs[5 * EDIM_];

// ---------------- PTX helpers (sm_103-base-safe only) ----------------
__device__ __forceinline__ uint32_t smem_u32(const void* p) {
    uint32_t a; asm("{ .reg .u64 t; cvta.to.shared.u64 t, %1; cvt.u32.u64 %0, t; }" : "=r"(a) : "l"(p)); return a;
}
#define CP_ASYNC16(dst, src) \
    asm volatile("cp.async.cg.shared.global [%0], [%1], 16;" :: "r"(dst), "l"(src))
#define CP_COMMIT() asm volatile("cp.async.commit_group;" ::: "memory")
#define CP_WAIT1()  asm volatile("cp.async.wait_group 1;" ::: "memory")

#define LDSM4(r0, r1, r2, r3, a) \
    asm volatile("ldmatrix.sync.aligned.m8n8.x4.shared.b16 {%0,%1,%2,%3}, [%4];" \
        : "=r"(r0), "=r"(r1), "=r"(r2), "=r"(r3) : "r"(a))

#define MMA16816(c, a, b0, b1) \
    asm volatile("mma.sync.aligned.m16n8k16.row.col.f32.bf16.bf16.f32 " \
        "{%0,%1,%2,%3},{%4,%5,%6,%7},{%8,%9},{%0,%1,%2,%3};" \
        : "+f"((c)[0]), "+f"((c)[1]), "+f"((c)[2]), "+f"((c)[3]) \
        : "r"((a)[0]), "r"((a)[1]), "r"((a)[2]), "r"((a)[3]), "r"(b0), "r"(b1))

// swizzled byte offset inside a 128-row x 128-byte tile
__device__ __forceinline__ uint32_t swz(uint32_t row, uint32_t bytecol) {
    return row * 128u + (bytecol ^ ((row & 7u) << 4));
}

// =====================================================================
// K1: compaction (sorted) + dirs normalization. 1 block, 256 thr.
// =====================================================================
__global__ void k_prep(const float* __restrict__ fps,
                       const float* __restrict__ penta)
{
    __shared__ int cnt_s[256];
    int t = threadIdx.x;

    int base = t * 16;
    unsigned mask16 = 0;
    int c = 0;
    #pragma unroll
    for (int i = 0; i < 16; ++i) {
        float f = fps[base + i];
        bool m = (f >= FPMIN_) && (f < FPMAX_);
        mask16 |= (m ? 1u : 0u) << i;
        c += m ? 1 : 0;
    }
    cnt_s[t] = c;
    __syncthreads();
    for (int d = 1; d < 256; d <<= 1) {
        int x = (t >= d) ? cnt_s[t - d] : 0;
        __syncthreads();
        cnt_s[t] += x;
        __syncthreads();
    }
    int off = cnt_s[t] - c;
    #pragma unroll
    for (int i = 0; i < 16; ++i)
        if (mask16 & (1u << i)) g_idx[off++] = base + i;

    if (t < 160) {
        int w = t >> 5, lane = t & 31;
        float s = 0.f;
        #pragma unroll
        for (int kk = 0; kk < 32; ++kk) {
            float x = penta[w * EDIM_ + kk * 32 + lane];
            s += x * x;
        }
        #pragma unroll
        for (int o = 16; o >= 1; o >>= 1) s += __shfl_xor_sync(0xffffffffu, s, o);
        float inv = rsqrtf(s);
        #pragma unroll
        for (int kk = 0; kk < 32; ++kk) {
            int id = w * EDIM_ + kk * 32 + lane;
            g_dirs[id] = penta[id] * inv;
        }
    }
}

// =====================================================================
// K1b: build [hi|lo|hi] bf16 rows for Wq|Wk|Wv (g_B2) and W_g1 (g_W1)
// grid 1600 x 256: rows 0..3199
// =====================================================================
__global__ void k_prepW(const float* __restrict__ Wq,
                        const float* __restrict__ Wk,
                        const float* __restrict__ Wv,
                        const float* __restrict__ W_g1)
{
    int id = blockIdx.x * 256 + threadIdx.x;
    int n  = id >> 7;                          // 0..3199
    int k4 = (id & 127) * 4;
    const float* W;
    int nn;
    __nv_bfloat16* dstbase;
    if (n < 1024)      { W = Wq;   nn = n;        dstbase = g_B2 + (size_t)n * KCAT; }
    else if (n < 2048) { W = Wk;   nn = n - 1024; dstbase = g_B2 + (size_t)n * KCAT; }
    else if (n < 3072) { W = Wv;   nn = n - 2048; dstbase = g_B2 + (size_t)n * KCAT; }
    else               { W = W_g1; nn = n - 3072; dstbase = g_W1 + (size_t)(n - 3072) * KCAT; }
    float4 v = *(const float4*)(W + (size_t)nn * 512 + k4);
    __nv_bfloat16 h0 = __float2bfloat16(v.x), h1 = __float2bfloat16(v.y);
    __nv_bfloat16 h2 = __float2bfloat16(v.z), h3 = __float2bfloat16(v.w);
    __nv_bfloat16 l0 = __float2bfloat16(v.x - __bfloat162float(h0));
    __nv_bfloat16 l1 = __float2bfloat16(v.y - __bfloat162float(h1));
    __nv_bfloat16 l2 = __float2bfloat16(v.z - __bfloat162float(h2));
    __nv_bfloat16 l3 = __float2bfloat16(v.w - __bfloat162float(h3));
    __nv_bfloat162* d0 = (__nv_bfloat162*)(dstbase + k4);
    __nv_bfloat162* d1 = (__nv_bfloat162*)(dstbase + 512 + k4);
    __nv_bfloat162* d2 = (__nv_bfloat162*)(dstbase + 1024 + k4);
    d0[0] = __nv_bfloat162(h0, h1); d0[1] = __nv_bfloat162(h2, h3);
    d1[0] = __nv_bfloat162(l0, l1); d1[1] = __nv_bfloat162(l2, l3);
    d2[0] = __nv_bfloat162(h0, h1); d2[1] = __nv_bfloat162(h2, h3);
}

// =====================================================================
// K2: gather tokens slice -> g_A2 [hi|hi|lo] (UNSCALED). 8 rows/block.
// =====================================================================
__global__ void k_gather(const float* __restrict__ tokens, int N, int M)
{
    int t = threadIdx.x;   // 128
    int r0 = blockIdx.x * 8;
    #pragma unroll
    for (int r = 0; r < 8; ++r) {
        int gr = r0 + r;
        float4 v = make_float4(0.f, 0.f, 0.f, 0.f);
        if (gr < M) {
            int b = gr / N, j = gr - b * N;
            int p = g_idx[j];
            v = *(const float4*)(tokens + ((size_t)b * P_ + p) * FULL_ + SLS_ + 4 * t);
        }
        __nv_bfloat16 h0 = __float2bfloat16(v.x), h1 = __float2bfloat16(v.y);
        __nv_bfloat16 h2 = __float2bfloat16(v.z), h3 = __float2bfloat16(v.w);
        __nv_bfloat16 l0 = __float2bfloat16(v.x - __bfloat162float(h0));
        __nv_bfloat16 l1 = __float2bfloat16(v.y - __bfloat162float(h1));
        __nv_bfloat16 l2 = __float2bfloat16(v.z - __bfloat162float(h2));
        __nv_bfloat16 l3 = __float2bfloat16(v.w - __bfloat162float(h3));
        size_t base = (size_t)gr * KCAT;
        int k4 = t * 4;
        __nv_bfloat162* d0 = (__nv_bfloat162*)(g_A2 + base + k4);
        __nv_bfloat162* d1 = (__nv_bfloat162*)(g_A2 + base + 512 + k4);
        __nv_bfloat162* d2 = (__nv_bfloat162*)(g_A2 + base + 1024 + k4);
        d0[0] = __nv_bfloat162(h0, h1); d0[1] = __nv_bfloat162(h2, h3);
        d1[0] = __nv_bfloat162(h0, h1); d1[1] = __nv_bfloat162(h2, h3);
        d2[0] = __nv_bfloat162(l0, l1); d2[1] = __nv_bfloat162(l2, l3);
    }
}

// =====================================================================
// K3a: gate h-GEMM via HMMA: h[32,128] tile = A''@W1''^T, then GELU +
//      reduce + sigmoid -> g_scale. grid = Mpad/32, 256 thr.
//      smem: 2 stages x (A 32x128B + B 128x128B) = 40 KB, swizzled.
// =====================================================================
#define GSTG 20480
__global__ void __launch_bounds__(256)
k_gate_mma(const float* __restrict__ b_g1,
           const float* __restrict__ W_g2,
           const float* __restrict__ b_g2,
           const float* __restrict__ alphap,
           int M)
{
    __shared__ __align__(128) char gsm[2 * GSTG];
    const uint32_t sbase = smem_u32(gsm);
    const int tid = threadIdx.x, lane = tid & 31, wid = tid >> 5;
    const int wm = wid & 1, wn = wid >> 1;     // 2 x 4 warps -> 32x128
    const int m0 = blockIdx.x * 32;

    const __nv_bfloat16* Ag = g_A2 + (size_t)m0 * KCAT;
    const int ldRow = tid >> 3, ldCh = (tid & 7) * 8;  // A: 1 unit, B: 4 units

    float acc[2][2][4];
    #pragma unroll
    for (int p = 0; p < 2; ++p)
        #pragma unroll
        for (int j = 0; j < 2; ++j)
            #pragma unroll
            for (int q = 0; q < 4; ++q) acc[p][j][q] = 0.f;

    // ---- stage loader ----
    auto load_st = [&](int s, int b) {
        uint32_t st = sbase + b * GSTG;
        if (ldRow < 32)
            CP_ASYNC16(st + swz(ldRow, ldCh * 2),
                       (const void*)(Ag + (size_t)ldRow * KCAT + s * 64 + ldCh));
        #pragma unroll
        for (int i = 0; i < 4; ++i) {
            int row = ldRow + i * 32;
            CP_ASYNC16(st + 4096 + swz(row, ldCh * 2),
                       (const void*)(g_W1 + (size_t)row * KCAT + s * 64 + ldCh));
        }
    };

    load_st(0, 0); CP_COMMIT();

    #pragma unroll 1
    for (int s = 0; s < 24; ++s) {
        if (s + 1 < 24) load_st(s + 1, (s + 1) & 1);
        CP_COMMIT();
        CP_WAIT1();
        __syncthreads();

        const uint32_t st = sbase + (s & 1) * GSTG;
        const uint32_t rowA = wm * 16 + (lane & 15);
        const uint32_t aRB = st + rowA * 128, xrA = (rowA & 7u) << 4;
        #pragma unroll
        for (int kk = 0; kk < 4; ++kk) {
            uint32_t a[4];
            uint32_t bcA = kk * 32 + (lane >> 4) * 16;
            LDSM4(a[0], a[1], a[2], a[3], aRB + (bcA ^ xrA));
            #pragma unroll
            for (int p = 0; p < 2; ++p) {
                uint32_t rowB = wn * 32 + p * 16 + ((lane >> 4) & 1) * 8 + (lane & 7);
                uint32_t bcB = kk * 32 + ((lane >> 3) & 1) * 16;
                uint32_t b0, b1, b2, b3;
                LDSM4(b0, b1, b2, b3, st + 4096 + swz(rowB, bcB));
                MMA16816(acc[p][0], a, b0, b1);
                MMA16816(acc[p][1], a, b2, b3);
            }
        }
        __syncthreads();
    }

    // ---- h tile -> smem (reuse gsm) ----
    float* hs = (float*)gsm;   // [32][132]
    {
        int r0h = wm * 16 + (lane >> 2);
        int cb  = wn * 32 + (lane & 3) * 2;
        #pragma unroll
        for (int p = 0; p < 2; ++p)
            #pragma unroll
            for (int j = 0; j < 2; ++j) {
                int c = cb + p * 16 + j * 8;
                hs[r0h * 132 + c]           = acc[p][j][0];
                hs[r0h * 132 + c + 1]       = acc[p][j][1];
                hs[(r0h + 8) * 132 + c]     = acc[p][j][2];
                hs[(r0h + 8) * 132 + c + 1] = acc[p][j][3];
            }
    }
    __syncthreads();

    // ---- GELU + dot(w2) + sigmoid -> scale ----
    float aw = 1.f / (1.f + expf(-alphap[0]));
    #pragma unroll
    for (int rr = 0; rr < 4; ++rr) {
        int r = wid * 4 + rr;
        float s = 0.f;
        #pragma unroll
        for (int q = 0; q < 4; ++q) {
            int c = lane + 32 * q;
            float x = hs[r * 132 + c] + b_g1[c];
            float h = 0.5f * x * (1.f + erff(x * 0.70710678118654752f));
            s += h * W_g2[c];
        }
        #pragma unroll
        for (int o = 16; o >= 1; o >>= 1) s += __shfl_xor_sync(0xffffffffu, s, o);
        if (lane == 0) {
            float gate = 1.f / (1.f + expf(-(s + b_g2[0])));
            g_scale[m0 + r] = gate * aw + (1.f - aw);
        }
    }
}

// =====================================================================
// K3b: main HMMA GEMM C[Mpad,3072] = A''@B''^T, scaled epilogue.
//      128x128 tile, BK=64, 3-stage cp.async, swizzled smem, 2 CTA/SM.
// =====================================================================
#define TILE_B    16384                  // 128 rows x 128 B
#define STAGE_B2  (2 * TILE_B)
#define NSTAGE    3
#define GEMM_SMEM (NSTAGE * STAGE_B2)    // 98304
#define NS        (KCAT / 64)            // 24

__global__ void __launch_bounds__(256, 2)
k_gemm_mma(float* __restrict__ out, int M)
{
    extern __shared__ char smem[];
    const uint32_t sb = smem_u32(smem);
    const int tid = threadIdx.x, lane = tid & 31;
    const int wid = tid >> 5;
    const int wm = wid & 3, wn = wid >> 2;          // 4 x 2 warp grid
    const int m0 = blockIdx.y * 128;
    const int n0 = blockIdx.x * 128;

    const __nv_bfloat16* Ag = g_A2 + (size_t)m0 * KCAT;
    const __nv_bfloat16* Bg = g_B2 + (size_t)n0 * KCAT;

    const int ldRow = tid >> 3, ldCh = (tid & 7) * 8;

    float acc[2][8][4];
    #pragma unroll
    for (int h = 0; h < 2; ++h)
        #pragma unroll
        for (int j = 0; j < 8; ++j)
            #pragma unroll
            for (int q = 0; q < 4; ++q) acc[h][j][q] = 0.f;

    // prologue stages 0,1
    #pragma unroll
    for (int pre = 0; pre < 2; ++pre) {
        uint32_t base = sb + pre * STAGE_B2;
        #pragma unroll
        for (int i = 0; i < 4; ++i) {
            int row = ldRow + i * 32;
            uint32_t doff = swz(row, ldCh * 2);
            CP_ASYNC16(base + doff, (const void*)(Ag + (size_t)row * KCAT + pre * 64 + ldCh));
            CP_ASYNC16(base + TILE_B + doff, (const void*)(Bg + (size_t)row * KCAT + pre * 64 + ldCh));
        }
        CP_COMMIT();
    }

    #pragma unroll 1
    for (int s = 0; s < NS; ++s) {
        CP_WAIT1();
        __syncthreads();
        if (s + 2 < NS) {
            uint32_t base = sb + ((s + 2) % NSTAGE) * STAGE_B2;
            #pragma unroll
            for (int i = 0; i < 4; ++i) {
                int row = ldRow + i * 32;
                uint32_t doff = swz(row, ldCh * 2);
                CP_ASYNC16(base + doff, (const void*)(Ag + (size_t)row * KCAT + (s + 2) * 64 + ldCh));
                CP_ASYNC16(base + TILE_B + doff, (const void*)(Bg + (size_t)row * KCAT + (s + 2) * 64 + ldCh));
            }
        }
        CP_COMMIT();

        const uint32_t stg = sb + (s % NSTAGE) * STAGE_B2;
        const uint32_t rowA0 = wm * 32 + (lane & 15);
        const uint32_t aRB0 = stg + rowA0 * 128, xrA0 = (rowA0 & 7u) << 4;
        const uint32_t aRB1 = aRB0 + 16 * 128;   // rowA0+16: same low-3 bits -> same xr
        #pragma unroll
        for (int kk = 0; kk < 4; ++kk) {
            uint32_t a0[4], a1[4];
            uint32_t bcA = kk * 32 + (lane >> 4) * 16;
            LDSM4(a0[0], a0[1], a0[2], a0[3], aRB0 + (bcA ^ xrA0));
            LDSM4(a1[0], a1[1], a1[2], a1[3], aRB1 + (bcA ^ xrA0));
            #pragma unroll
            for (int p = 0; p < 4; ++p) {
                uint32_t rowB = wn * 64 + p * 16 + ((lane >> 4) & 1) * 8 + (lane & 7);
                uint32_t bcB = kk * 32 + ((lane >> 3) & 1) * 16;
                uint32_t b0, b1, b2, b3;
                LDSM4(b0, b1, b2, b3, stg + TILE_B + swz(rowB, bcB));
                MMA16816(acc[0][2 * p],     a0, b0, b1);
                MMA16816(acc[0][2 * p + 1], a0, b2, b3);
                MMA16816(acc[1][2 * p],     a1, b0, b1);
                MMA16816(acc[1][2 * p + 1], a1, b2, b3);
            }
        }
        __syncthreads();
    }

    // ---- epilogue: apply per-row gate scale, store ----
    const int sel  = n0 >> 10;
    const int ncolB = (n0 & 1023) + wn * 64;
    float* outM = out + (size_t)sel * M * EDIM_;
    #pragma unroll
    for (int h = 0; h < 2; ++h) {
        int rbase = m0 + wm * 32 + h * 16 + (lane >> 2);
        #pragma unroll
        for (int rr = 0; rr < 2; ++rr) {
            int grow = rbase + rr * 8;
            if (grow < M) {
                float sc = g_scale[grow];
                float* orow = outM + (size_t)grow * EDIM_ + ncolB + 2 * (lane & 3);
                #pragma unroll
                for (int j = 0; j < 8; ++j) {
                    float2 v = make_float2(acc[h][j][2 * rr] * sc, acc[h][j][2 * rr + 1] * sc);
                    *(float2*)(orow + j * 8) = v;
                }
            }
        }
    }
}

// =====================================================================
// K4: pentachoron projections (float4). One warp per QKV row.
// =====================================================================
__global__ void k_proj(float* __restrict__ out, int N)
{
    __shared__ float4 ds[5 * 256];
    int t = threadIdx.x;  // 256
    for (int i = t; i < 5 * 256; i += 256) ds[i] = ((const float4*)g_dirs)[i];
    __syncthreads();

    int w = t >> 5, lane = t & 31;
    long long g = (long long)blockIdx.x * 8 + w;
    long long R = 12LL * N;
    if (g >= R) return;

    const float4* row = (const float4*)(out + g * EDIM_);
    float acc[5] = {0.f, 0.f, 0.f, 0.f, 0.f};
    #pragma unroll
    for (int it = 0; it < 8; ++it) {
        int idx = it * 32 + lane;
        float4 x = row[idx];
        #pragma unroll
        for (int v = 0; v < 5; ++v) {
            float4 d = ds[v * 256 + idx];
            acc[v] += x.x * d.x + x.y * d.y + x.z * d.z + x.w * d.w;
        }
    }
    #pragma unroll
    for (int v = 0; v < 5; ++v)
        #pragma unroll
        for (int o = 16; o >= 1; o >>= 1)
            acc[v] += __shfl_xor_sync(0xffffffffu, acc[v], o);

    if (lane == 0) {
        long long fourN = 4LL * N;
        int sel = (int)(g / fourN);
        long long r = g - (long long)sel * fourN;
        size_t base = (size_t)12 * N * EDIM_ + (size_t)sel * 5 * fourN;
        #pragma unroll
        for (int v = 0; v < 5; ++v)
            out[base + (size_t)v * fourN + r] = acc[v];
    }
}

// =====================================================================
extern "C" void kernel_launch(void* const* d_in, const int* in_sizes, int n_in,
                              void* d_out, int out_size)
{
    const float* tokens = (const float*)d_in[0];
    const float* fps    = (const float*)d_in[1];
    const float* W_g1   = (const float*)d_in[2];
    const float* b_g1   = (const float*)d_in[3];
    const float* W_g2   = (const float*)d_in[4];
    const float* b_g2   = (const float*)d_in[5];
    const float* alpha  = (const float*)d_in[6];
    const float* Wq     = (const float*)d_in[7];
    const float* Wk     = (const float*)d_in[8];
    const float* Wv     = (const float*)d_in[9];
    const float* penta  = (const float*)d_in[10];

    int N = out_size / 12348;       // per token: 3*1024 QKV + 3*5 projections
    if (N <= 0) return;
    int M = 4 * N;
    int Mpad = (M + 127) & ~127;
    float* out = (float*)d_out;

    cudaFuncSetAttribute(k_gemm_mma, cudaFuncAttributeMaxDynamicSharedMemorySize, GEMM_SMEM);

    k_prep<<<1, 256>>>(fps, penta);
    k_prepW<<<1600, 256>>>(Wq, Wk, Wv, W_g1);
    k_gather<<<Mpad / 8, 128>>>(tokens, N, M);
    k_gate_mma<<<Mpad / 32, 256>>>(b_g1, W_g2, b_g2, alpha, M);
    dim3 g3(24, Mpad / 128);
    k_gemm_mma<<<g3, 256, GEMM_SMEM>>>(out, M);
    k_proj<<<(int)((12LL * N + 7) / 8), 256>>>(out, N);
}

// round 5
// speedup vs baseline: 4.3029x; 1.3438x over previous
#include <cuda_runtime.h>
#include <cuda_fp16.h>
#include <cstdint>
#include <math.h>

// ---------------- problem constants ----------------
#define B_      4
#define P_      4096
#define FULL_   4096
#define SLICE_  512
#define EDIM_   1024
#define SLS_    1024          // slice start
#define FPMIN_  0.1875f
#define FPMAX_  0.4375f
#define KCAT    1024          // A physical K = [hi|lo]
#define KB_     512           // B physical K (hi only, chunk-repeated)
#define MPADMX  4096

// ---------------- scratch (no allocs allowed) ----------------
__device__ __align__(16) __half g_A2[(size_t)B_ * P_ * KCAT];   // [Ah|Al], exact split
__device__ __align__(16) __half g_B2[(size_t)3 * EDIM_ * KB_];  // Wq|Wk|Wv hi
__device__ __align__(16) __half g_W1[(size_t)128 * KB_];        // W_g1 hi
__device__ float g_pp[5 * 48 * MPADMX];                          // proj partials
__device__ float g_scale[B_ * P_ + 128];
__device__ int   g_idx[P_];
__device__ __align__(16) float g_dirs[5 * EDIM_];

// ---------------- PTX helpers (sm_103-base-safe only) ----------------
__device__ __forceinline__ uint32_t smem_u32(const void* p) {
    uint32_t a; asm("{ .reg .u64 t; cvta.to.shared.u64 t, %1; cvt.u32.u64 %0, t; }" : "=r"(a) : "l"(p)); return a;
}
#define CP_ASYNC16(dst, src) \
    asm volatile("cp.async.cg.shared.global [%0], [%1], 16;" :: "r"(dst), "l"(src))
#define CP_COMMIT() asm volatile("cp.async.commit_group;" ::: "memory")
#define CP_WAIT1()  asm volatile("cp.async.wait_group 1;" ::: "memory")

#define LDSM4(r0, r1, r2, r3, a) \
    asm volatile("ldmatrix.sync.aligned.m8n8.x4.shared.b16 {%0,%1,%2,%3}, [%4];" \
        : "=r"(r0), "=r"(r1), "=r"(r2), "=r"(r3) : "r"(a))

#define MMA16816(c, a, b0, b1) \
    asm volatile("mma.sync.aligned.m16n8k16.row.col.f32.f16.f16.f32 " \
        "{%0,%1,%2,%3},{%4,%5,%6,%7},{%8,%9},{%0,%1,%2,%3};" \
        : "+f"((c)[0]), "+f"((c)[1]), "+f"((c)[2]), "+f"((c)[3]) \
        : "r"((a)[0]), "r"((a)[1]), "r"((a)[2]), "r"((a)[3]), "r"(b0), "r"(b1))

__device__ __forceinline__ uint32_t swz(uint32_t row, uint32_t bytecol) {
    return row * 128u + (bytecol ^ ((row & 7u) << 4));
}

// =====================================================================
// K1: compaction (sorted) + dirs normalization. 1 block, 256 thr.
// =====================================================================
__global__ void k_prep(const float* __restrict__ fps,
                       const float* __restrict__ penta)
{
    __shared__ int cnt_s[256];
    int t = threadIdx.x;

    int base = t * 16;
    unsigned mask16 = 0;
    int c = 0;
    #pragma unroll
    for (int i = 0; i < 16; ++i) {
        float f = fps[base + i];
        bool m = (f >= FPMIN_) && (f < FPMAX_);
        mask16 |= (m ? 1u : 0u) << i;
        c += m ? 1 : 0;
    }
    cnt_s[t] = c;
    __syncthreads();
    for (int d = 1; d < 256; d <<= 1) {
        int x = (t >= d) ? cnt_s[t - d] : 0;
        __syncthreads();
        cnt_s[t] += x;
        __syncthreads();
    }
    int off = cnt_s[t] - c;
    #pragma unroll
    for (int i = 0; i < 16; ++i)
        if (mask16 & (1u << i)) g_idx[off++] = base + i;

    if (t < 160) {
        int w = t >> 5, lane = t & 31;
        float s = 0.f;
        #pragma unroll
        for (int kk = 0; kk < 32; ++kk) {
            float x = penta[w * EDIM_ + kk * 32 + lane];
            s += x * x;
        }
        #pragma unroll
        for (int o = 16; o >= 1; o >>= 1) s += __shfl_xor_sync(0xffffffffu, s, o);
        float inv = rsqrtf(s);
        #pragma unroll
        for (int kk = 0; kk < 32; ++kk) {
            int id = w * EDIM_ + kk * 32 + lane;
            g_dirs[id] = penta[id] * inv;
        }
    }
}

// =====================================================================
// K1b: fp16(hi) conversion of Wq|Wk|Wv -> g_B2 and W_g1 -> g_W1
// grid 1600 x 256 : 3200 rows x 512 cols, 4 cols/thread
// =====================================================================
__global__ void k_prepW(const float* __restrict__ Wq,
                        const float* __restrict__ Wk,
                        const float* __restrict__ Wv,
                        const float* __restrict__ W_g1)
{
    int id = blockIdx.x * 256 + threadIdx.x;
    int n  = id >> 7;                          // 0..3199
    int k4 = (id & 127) * 4;
    const float* W;
    int nn;
    __half* dst;
    if (n < 1024)      { W = Wq;   nn = n;        dst = g_B2 + (size_t)n * KB_; }
    else if (n < 2048) { W = Wk;   nn = n - 1024; dst = g_B2 + (size_t)n * KB_; }
    else if (n < 3072) { W = Wv;   nn = n - 2048; dst = g_B2 + (size_t)n * KB_; }
    else               { W = W_g1; nn = n - 3072; dst = g_W1 + (size_t)(n - 3072) * KB_; }
    float4 v = *(const float4*)(W + (size_t)nn * 512 + k4);
    __half2* d = (__half2*)(dst + k4);
    d[0] = __half2(__float2half(v.x), __float2half(v.y));
    d[1] = __half2(__float2half(v.z), __float2half(v.w));
}

// =====================================================================
// K2: gather tokens slice -> g_A2 = [Ah | Al] (exact fp16 split)
// =====================================================================
__global__ void k_gather(const float* __restrict__ tokens, int N, int M)
{
    int t = threadIdx.x;   // 128
    int r0 = blockIdx.x * 8;
    #pragma unroll
    for (int r = 0; r < 8; ++r) {
        int gr = r0 + r;
        float4 v = make_float4(0.f, 0.f, 0.f, 0.f);
        if (gr < M) {
            int b = gr / N, j = gr - b * N;
            int p = g_idx[j];
            v = *(const float4*)(tokens + ((size_t)b * P_ + p) * FULL_ + SLS_ + 4 * t);
        }
        __half h0 = __float2half(v.x), h1 = __float2half(v.y);
        __half h2 = __float2half(v.z), h3 = __float2half(v.w);
        __half l0 = __float2half(v.x - __half2float(h0));
        __half l1 = __float2half(v.y - __half2float(h1));
        __half l2 = __float2half(v.z - __half2float(h2));
        __half l3 = __float2half(v.w - __half2float(h3));
        size_t base = (size_t)gr * KCAT;
        int k4 = t * 4;
        __half2* dh = (__half2*)(g_A2 + base + k4);
        __half2* dl = (__half2*)(g_A2 + base + 512 + k4);
        dh[0] = __half2(h0, h1); dh[1] = __half2(h2, h3);
        dl[0] = __half2(l0, l1); dl[1] = __half2(l2, l3);
    }
}

// =====================================================================
// K3a: gate h-GEMM via HMMA (32x128 tile, K=1024, B period 512),
//      then GELU + reduce + sigmoid -> g_scale. grid = Mpad/32.
// =====================================================================
#define GSTG   20480
#define GSMEM  (3 * GSTG)
__global__ void __launch_bounds__(256)
k_gate_mma(const float* __restrict__ b_g1,
           const float* __restrict__ W_g2,
           const float* __restrict__ b_g2,
           const float* __restrict__ alphap,
           int M)
{
    extern __shared__ char gsm[];
    const uint32_t sbase = smem_u32(gsm);
    const int tid = threadIdx.x, lane = tid & 31, wid = tid >> 5;
    const int wm = wid & 1, wn = wid >> 1;     // 2 x 4 warps -> 32x128
    const int m0 = blockIdx.x * 32;

    const __half* Ag = g_A2 + (size_t)m0 * KCAT;
    const int ldRow = tid >> 3, ldCh = (tid & 7) * 8;

    float acc[2][2][4];
    #pragma unroll
    for (int p = 0; p < 2; ++p)
        #pragma unroll
        for (int j = 0; j < 2; ++j)
            #pragma unroll
            for (int q = 0; q < 4; ++q) acc[p][j][q] = 0.f;

    auto load_st = [&](int s, int b) {
        uint32_t st = sbase + b * GSTG;
        CP_ASYNC16(st + swz(ldRow, ldCh * 2),
                   (const void*)(Ag + (size_t)ldRow * KCAT + s * 64 + ldCh));
        int bo = (s & 7) * 64;
        #pragma unroll
        for (int i = 0; i < 4; ++i) {
            int row = ldRow + i * 32;
            CP_ASYNC16(st + 4096 + swz(row, ldCh * 2),
                       (const void*)(g_W1 + (size_t)row * KB_ + bo + ldCh));
        }
    };

    load_st(0, 0); CP_COMMIT();
    load_st(1, 1); CP_COMMIT();

    #pragma unroll 1
    for (int s = 0; s < 16; ++s) {
        CP_WAIT1();
        __syncthreads();
        if (s + 2 < 16) load_st(s + 2, (s + 2) % 3);
        CP_COMMIT();

        const uint32_t st = sbase + (s % 3) * GSTG;
        const uint32_t rowA = wm * 16 + (lane & 15);
        const uint32_t aRB = st + rowA * 128, xrA = (rowA & 7u) << 4;
        #pragma unroll
        for (int kk = 0; kk < 4; ++kk) {
            uint32_t a[4];
            uint32_t bcA = kk * 32 + (lane >> 4) * 16;
            LDSM4(a[0], a[1], a[2], a[3], aRB + (bcA ^ xrA));
            #pragma unroll
            for (int p = 0; p < 2; ++p) {
                uint32_t rowB = wn * 32 + p * 16 + ((lane >> 4) & 1) * 8 + (lane & 7);
                uint32_t bcB = kk * 32 + ((lane >> 3) & 1) * 16;
                uint32_t b0, b1, b2, b3;
                LDSM4(b0, b1, b2, b3, st + 4096 + swz(rowB, bcB));
                MMA16816(acc[p][0], a, b0, b1);
                MMA16816(acc[p][1], a, b2, b3);
            }
        }
        __syncthreads();
    }

    // ---- h tile -> smem ----
    float* hs = (float*)gsm;   // [32][132]
    {
        int r0h = wm * 16 + (lane >> 2);
        int cb  = wn * 32 + (lane & 3) * 2;
        #pragma unroll
        for (int p = 0; p < 2; ++p)
            #pragma unroll
            for (int j = 0; j < 2; ++j) {
                int c = cb + p * 16 + j * 8;
                hs[r0h * 132 + c]           = acc[p][j][0];
                hs[r0h * 132 + c + 1]       = acc[p][j][1];
                hs[(r0h + 8) * 132 + c]     = acc[p][j][2];
                hs[(r0h + 8) * 132 + c + 1] = acc[p][j][3];
            }
    }
    __syncthreads();

    // ---- GELU + dot(w2) + sigmoid -> scale ----
    float aw = 1.f / (1.f + expf(-alphap[0]));
    #pragma unroll
    for (int rr = 0; rr < 4; ++rr) {
        int r = wid * 4 + rr;
        float s = 0.f;
        #pragma unroll
        for (int q = 0; q < 4; ++q) {
            int c = lane + 32 * q;
            float x = hs[r * 132 + c] + b_g1[c];
            float h = 0.5f * x * (1.f + erff(x * 0.70710678118654752f));
            s += h * W_g2[c];
        }
        #pragma unroll
        for (int o = 16; o >= 1; o >>= 1) s += __shfl_xor_sync(0xffffffffu, s, o);
        if (lane == 0) {
            float gate = 1.f / (1.f + expf(-(s + b_g2[0])));
            g_scale[m0 + r] = gate * aw + (1.f - aw);
        }
    }
}

// =====================================================================
// K3b: main HMMA GEMM C[Mpad,3072] = A''@B''^T (K=1024, B period 512),
//      scaled epilogue + fused pentachoron partials into g_pp.
// =====================================================================
#define TILE_B    16384
#define STAGE_B2  (2 * TILE_B)
#define NSTAGE    3
#define GEMM_SMEM (NSTAGE * STAGE_B2)    // 98304
#define NS        (KCAT / 64)            // 16

__global__ void __launch_bounds__(256, 2)
k_gemm_mma(float* __restrict__ out, int M)
{
    extern __shared__ char smem[];
    const uint32_t sb = smem_u32(smem);
    const int tid = threadIdx.x, lane = tid & 31;
    const int wid = tid >> 5;
    const int wm = wid & 3, wn = wid >> 2;          // 4 x 2 warp grid
    const int m0 = blockIdx.y * 128;
    const int n0 = blockIdx.x * 128;

    const __half* Ag = g_A2 + (size_t)m0 * KCAT;
    const __half* Bg = g_B2 + (size_t)n0 * KB_;

    const int ldRow = tid >> 3, ldCh = (tid & 7) * 8;

    float acc[2][8][4];
    #pragma unroll
    for (int h = 0; h < 2; ++h)
        #pragma unroll
        for (int j = 0; j < 8; ++j)
            #pragma unroll
            for (int q = 0; q < 4; ++q) acc[h][j][q] = 0.f;

    #pragma unroll
    for (int pre = 0; pre < 2; ++pre) {
        uint32_t base = sb + pre * STAGE_B2;
        int bo = (pre & 7) * 64;
        #pragma unroll
        for (int i = 0; i < 4; ++i) {
            int row = ldRow + i * 32;
            uint32_t doff = swz(row, ldCh * 2);
            CP_ASYNC16(base + doff, (const void*)(Ag + (size_t)row * KCAT + pre * 64 + ldCh));
            CP_ASYNC16(base + TILE_B + doff, (const void*)(Bg + (size_t)row * KB_ + bo + ldCh));
        }
        CP_COMMIT();
    }

    #pragma unroll 1
    for (int s = 0; s < NS; ++s) {
        CP_WAIT1();
        __syncthreads();
        if (s + 2 < NS) {
            uint32_t base = sb + ((s + 2) % NSTAGE) * STAGE_B2;
            int bo = ((s + 2) & 7) * 64;
            #pragma unroll
            for (int i = 0; i < 4; ++i) {
                int row = ldRow + i * 32;
                uint32_t doff = swz(row, ldCh * 2);
                CP_ASYNC16(base + doff, (const void*)(Ag + (size_t)row * KCAT + (s + 2) * 64 + ldCh));
                CP_ASYNC16(base + TILE_B + doff, (const void*)(Bg + (size_t)row * KB_ + bo + ldCh));
            }
        }
        CP_COMMIT();

        const uint32_t stg = sb + (s % NSTAGE) * STAGE_B2;
        const uint32_t rowA0 = wm * 32 + (lane & 15);
        const uint32_t aRB0 = stg + rowA0 * 128, xrA0 = (rowA0 & 7u) << 4;
        const uint32_t aRB1 = aRB0 + 16 * 128;
        #pragma unroll
        for (int kk = 0; kk < 4; ++kk) {
            uint32_t a0[4], a1[4];
            uint32_t bcA = kk * 32 + (lane >> 4) * 16;
            LDSM4(a0[0], a0[1], a0[2], a0[3], aRB0 + (bcA ^ xrA0));
            LDSM4(a1[0], a1[1], a1[2], a1[3], aRB1 + (bcA ^ xrA0));
            #pragma unroll
            for (int p = 0; p < 4; ++p) {
                uint32_t rowB = wn * 64 + p * 16 + ((lane >> 4) & 1) * 8 + (lane & 7);
                uint32_t bcB = kk * 32 + ((lane >> 3) & 1) * 16;
                uint32_t b0, b1, b2, b3;
                LDSM4(b0, b1, b2, b3, stg + TILE_B + swz(rowB, bcB));
                MMA16816(acc[0][2 * p],     a0, b0, b1);
                MMA16816(acc[0][2 * p + 1], a0, b2, b3);
                MMA16816(acc[1][2 * p],     a1, b0, b1);
                MMA16816(acc[1][2 * p + 1], a1, b2, b3);
            }
        }
        __syncthreads();
    }

    // ---- dirs slice into smem ----
    float* ds = (float*)smem;            // [5][128]
    const int ncol0 = n0 & 1023;
    for (int i = tid; i < 640; i += 256) {
        int v = i >> 7, l = i & 127;
        ds[i] = g_dirs[v * EDIM_ + ncol0 + l];
    }
    __syncthreads();

    // ---- epilogue: scale, store, fused proj partials ----
    const int sel  = n0 >> 10;
    const int ncolB = ncol0 + wn * 64;
    const int chunk = blockIdx.x * 2 + wn;          // 0..47
    float* outM = out + (size_t)sel * M * EDIM_;
    #pragma unroll
    for (int h = 0; h < 2; ++h) {
        #pragma unroll
        for (int rr = 0; rr < 2; ++rr) {
            int grow = m0 + wm * 32 + h * 16 + rr * 8 + (lane >> 2);
            float sc = g_scale[grow];
            bool ok = grow < M;
            float* orow = outM + (size_t)grow * EDIM_ + ncolB + 2 * (lane & 3);
            float p0 = 0.f, p1 = 0.f, p2 = 0.f, p3 = 0.f, p4 = 0.f;
            #pragma unroll
            for (int j = 0; j < 8; ++j) {
                float c0 = acc[h][j][2 * rr] * sc;
                float c1 = acc[h][j][2 * rr + 1] * sc;
                if (ok) *(float2*)(orow + j * 8) = make_float2(c0, c1);
                int lc = wn * 64 + j * 8 + 2 * (lane & 3);
                p0 += c0 * ds[lc]       + c1 * ds[lc + 1];
                p1 += c0 * ds[128 + lc] + c1 * ds[128 + lc + 1];
                p2 += c0 * ds[256 + lc] + c1 * ds[256 + lc + 1];
                p3 += c0 * ds[384 + lc] + c1 * ds[384 + lc + 1];
                p4 += c0 * ds[512 + lc] + c1 * ds[512 + lc + 1];
            }
            p0 += __shfl_xor_sync(0xffffffffu, p0, 1); p0 += __shfl_xor_sync(0xffffffffu, p0, 2);
            p1 += __shfl_xor_sync(0xffffffffu, p1, 1); p1 += __shfl_xor_sync(0xffffffffu, p1, 2);
            p2 += __shfl_xor_sync(0xffffffffu, p2, 1); p2 += __shfl_xor_sync(0xffffffffu, p2, 2);
            p3 += __shfl_xor_sync(0xffffffffu, p3, 1); p3 += __shfl_xor_sync(0xffffffffu, p3, 2);
            p4 += __shfl_xor_sync(0xffffffffu, p4, 1); p4 += __shfl_xor_sync(0xffffffffu, p4, 2);
            if (ok && (lane & 3) == 0) {
                g_pp[(0 * 48 + chunk) * MPADMX + grow] = p0;
                g_pp[(1 * 48 + chunk) * MPADMX + grow] = p1;
                g_pp[(2 * 48 + chunk) * MPADMX + grow] = p2;
                g_pp[(3 * 48 + chunk) * MPADMX + grow] = p3;
                g_pp[(4 * 48 + chunk) * MPADMX + grow] = p4;
            }
        }
    }
}

// =====================================================================
// K4: finalize projections: sum 16 chunks per (sel, v, row)
// =====================================================================
__global__ void k_fin(float* __restrict__ out, int N, int M)
{
    int sv = blockIdx.y;            // 0..14
    int sel = sv / 5, v = sv % 5;
    int row = blockIdx.x * 256 + threadIdx.x;
    if (row >= M) return;
    const float* src = g_pp + ((size_t)v * 48 + sel * 16) * MPADMX + row;
    float s = 0.f;
    #pragma unroll
    for (int g = 0; g < 16; ++g) s += src[(size_t)g * MPADMX];
    size_t base = (size_t)3 * M * EDIM_ + (size_t)sel * 5 * M + (size_t)v * M;
    out[base + row] = s;
}

// =====================================================================
extern "C" void kernel_launch(void* const* d_in, const int* in_sizes, int n_in,
                              void* d_out, int out_size)
{
    const float* tokens = (const float*)d_in[0];
    const float* fps    = (const float*)d_in[1];
    const float* W_g1   = (const float*)d_in[2];
    const float* b_g1   = (const float*)d_in[3];
    const float* W_g2   = (const float*)d_in[4];
    const float* b_g2   = (const float*)d_in[5];
    const float* alpha  = (const float*)d_in[6];
    const float* Wq     = (const float*)d_in[7];
    const float* Wk     = (const float*)d_in[8];
    const float* Wv     = (const float*)d_in[9];
    const float* penta  = (const float*)d_in[10];

    int N = out_size / 12348;       // per token: 3*1024 QKV + 3*5 projections
    if (N <= 0) return;
    int M = 4 * N;
    int Mpad = (M + 127) & ~127;
    float* out = (float*)d_out;

    cudaFuncSetAttribute(k_gemm_mma, cudaFuncAttributeMaxDynamicSharedMemorySize, GEMM_SMEM);
    cudaFuncSetAttribute(k_gate_mma, cudaFuncAttributeMaxDynamicSharedMemorySize, GSMEM);

    k_prep<<<1, 256>>>(fps, penta);
    k_prepW<<<1600, 256>>>(Wq, Wk, Wv, W_g1);
    k_gather<<<Mpad / 8, 128>>>(tokens, N, M);
    k_gate_mma<<<Mpad / 32, 256, GSMEM>>>(b_g1, W_g2, b_g2, alpha, M);
    dim3 g3(24, Mpad / 128);
    k_gemm_mma<<<g3, 256, GEMM_SMEM>>>(out, M);
    dim3 gf((M + 255) / 256, 15);
    k_fin<<<gf, 256>>>(out, N, M);
}

// round 6
// speedup vs baseline: 6.6650x; 1.5489x over previous
#include <cuda_runtime.h>
#include <cuda_fp16.h>
#include <cstdint>
#include <math.h>

// ---------------- problem constants ----------------
#define B_      4
#define P_      4096
#define FULL_   4096
#define SLICE_  512
#define EDIM_   1024
#define SLS_    1024          // slice start
#define FPMIN_  0.1875f
#define FPMAX_  0.4375f
#define KB_     512           // K for all GEMMs (fp16 hi only)
#define MPADMX  4096

// ---------------- scratch (no allocs allowed) ----------------
__device__ __align__(16) __half g_A2[(size_t)B_ * P_ * KB_];    // gathered slice, fp16
__device__ __align__(16) __half g_B2[(size_t)3 * EDIM_ * KB_];  // Wq|Wk|Wv fp16
__device__ __align__(16) __half g_W1[(size_t)128 * KB_];        // W_g1 fp16
__device__ float g_pp[5 * 48 * MPADMX];                          // proj partials
__device__ float g_scale[B_ * P_ + 128];
__device__ int   g_idx[P_];
__device__ __align__(16) float g_dirs[5 * EDIM_];

// ---------------- PTX helpers (sm_103-base-safe only) ----------------
__device__ __forceinline__ uint32_t smem_u32(const void* p) {
    uint32_t a; asm("{ .reg .u64 t; cvta.to.shared.u64 t, %1; cvt.u32.u64 %0, t; }" : "=r"(a) : "l"(p)); return a;
}
#define CP_ASYNC16(dst, src) \
    asm volatile("cp.async.cg.shared.global [%0], [%1], 16;" :: "r"(dst), "l"(src))
#define CP_COMMIT() asm volatile("cp.async.commit_group;" ::: "memory")
#define CP_WAIT1()  asm volatile("cp.async.wait_group 1;" ::: "memory")
#define CP_WAIT0()  asm volatile("cp.async.wait_group 0;" ::: "memory")

#define LDSM4(r0, r1, r2, r3, a) \
    asm volatile("ldmatrix.sync.aligned.m8n8.x4.shared.b16 {%0,%1,%2,%3}, [%4];" \
        : "=r"(r0), "=r"(r1), "=r"(r2), "=r"(r3) : "r"(a))

#define MMA16816(c, a, b0, b1) \
    asm volatile("mma.sync.aligned.m16n8k16.row.col.f32.f16.f16.f32 " \
        "{%0,%1,%2,%3},{%4,%5,%6,%7},{%8,%9},{%0,%1,%2,%3};" \
        : "+f"((c)[0]), "+f"((c)[1]), "+f"((c)[2]), "+f"((c)[3]) \
        : "r"((a)[0]), "r"((a)[1]), "r"((a)[2]), "r"((a)[3]), "r"(b0), "r"(b1))

__device__ __forceinline__ uint32_t swz(uint32_t row, uint32_t bytecol) {
    return row * 128u + (bytecol ^ ((row & 7u) << 4));
}

// =====================================================================
// K1: merged prep. Block 0: compaction + dirs. Blocks 1..1600: fp16
//     conversion of Wq|Wk|Wv -> g_B2 and W_g1 -> g_W1.
// =====================================================================
__global__ void k_prep(const float* __restrict__ fps,
                       const float* __restrict__ penta,
                       const float* __restrict__ Wq,
                       const float* __restrict__ Wk,
                       const float* __restrict__ Wv,
                       const float* __restrict__ W_g1)
{
    int t = threadIdx.x;
    if (blockIdx.x != 0) {
        int id = (blockIdx.x - 1) * 256 + t;
        int n  = id >> 7;                          // 0..3199
        int k4 = (id & 127) * 4;
        const float* W;
        int nn;
        __half* dst;
        if (n < 1024)      { W = Wq;   nn = n;        dst = g_B2 + (size_t)n * KB_; }
        else if (n < 2048) { W = Wk;   nn = n - 1024; dst = g_B2 + (size_t)n * KB_; }
        else if (n < 3072) { W = Wv;   nn = n - 2048; dst = g_B2 + (size_t)n * KB_; }
        else               { W = W_g1; nn = n - 3072; dst = g_W1 + (size_t)(n - 3072) * KB_; }
        float4 v = *(const float4*)(W + (size_t)nn * 512 + k4);
        __half2* d = (__half2*)(dst + k4);
        d[0] = __half2(__float2half(v.x), __float2half(v.y));
        d[1] = __half2(__float2half(v.z), __float2half(v.w));
        return;
    }

    __shared__ int cnt_s[256];
    int base = t * 16;
    unsigned mask16 = 0;
    int c = 0;
    #pragma unroll
    for (int i = 0; i < 16; ++i) {
        float f = fps[base + i];
        bool m = (f >= FPMIN_) && (f < FPMAX_);
        mask16 |= (m ? 1u : 0u) << i;
        c += m ? 1 : 0;
    }
    cnt_s[t] = c;
    __syncthreads();
    for (int d = 1; d < 256; d <<= 1) {
        int x = (t >= d) ? cnt_s[t - d] : 0;
        __syncthreads();
        cnt_s[t] += x;
        __syncthreads();
    }
    int off = cnt_s[t] - c;
    #pragma unroll
    for (int i = 0; i < 16; ++i)
        if (mask16 & (1u << i)) g_idx[off++] = base + i;

    if (t < 160) {
        int w = t >> 5, lane = t & 31;
        float s = 0.f;
        #pragma unroll
        for (int kk = 0; kk < 32; ++kk) {
            float x = penta[w * EDIM_ + kk * 32 + lane];
            s += x * x;
        }
        #pragma unroll
        for (int o = 16; o >= 1; o >>= 1) s += __shfl_xor_sync(0xffffffffu, s, o);
        float inv = rsqrtf(s);
        #pragma unroll
        for (int kk = 0; kk < 32; ++kk) {
            int id = w * EDIM_ + kk * 32 + lane;
            g_dirs[id] = penta[id] * inv;
        }
    }
}

// =====================================================================
// K2: fused gather + gate. 32 rows/block, 256 thr.
// smem: A 32KB (8 chunks x [32 x 128B] swz) | W1 128KB (8 chunks x 16KB)
// =====================================================================
#define GA_SM   32768
#define GSMEM   (GA_SM + 131072)
__global__ void __launch_bounds__(256, 1)
k_gategather(const float* __restrict__ tokens,
             const float* __restrict__ b_g1,
             const float* __restrict__ W_g2,
             const float* __restrict__ b_g2,
             const float* __restrict__ alphap,
             int N, int M)
{
    extern __shared__ char gsm[];
    const uint32_t sbase = smem_u32(gsm);
    const int tid = threadIdx.x, lane = tid & 31, wid = tid >> 5;
    const int wm = wid & 1, wn = wid >> 1;     // 2 x 4 warps -> 32x128
    const int m0 = blockIdx.x * 32;

    // ---- B: async copy full W_g1 into smem (8 chunks of [128 x 128B] swz)
    #pragma unroll
    for (int i = 0; i < 32; ++i) {
        int u = tid + i * 256;                 // 16B unit, 0..8191
        int ch = u >> 10;                      // chunk 0..7
        int rowB = (u & 1023) >> 3;            // 0..127
        int kc = (u & 7) * 8;                  // k within chunk (halfs)
        CP_ASYNC16(sbase + GA_SM + ch * 16384 + swz((uint32_t)rowB, (uint32_t)kc * 2),
                   (const void*)(g_W1 + (size_t)rowB * KB_ + ch * 64 + kc));
    }
    CP_COMMIT();

    // ---- A: gather + convert. thread: row = tid>>3, chunk = tid&7 (64 k)
    {
        int r = tid >> 3, ch = tid & 7;
        int gr = m0 + r;
        const float4* src = nullptr;
        if (gr < M) {
            int b = gr / N, j = gr - b * N;
            int p = g_idx[j];
            src = (const float4*)(tokens + ((size_t)b * P_ + p) * FULL_ + SLS_ + ch * 64);
        }
        __half2 hv[32];
        #pragma unroll
        for (int i = 0; i < 16; ++i) {
            float4 v = src ? src[i] : make_float4(0.f, 0.f, 0.f, 0.f);
            hv[2 * i]     = __half2(__float2half(v.x), __float2half(v.y));
            hv[2 * i + 1] = __half2(__float2half(v.z), __float2half(v.w));
        }
        #pragma unroll
        for (int u = 0; u < 8; ++u) {
            uint32_t o = (uint32_t)(ch * 4096) + swz((uint32_t)r, (uint32_t)(u * 16));
            *(uint4*)(gsm + o) = *(uint4*)&hv[u * 4];
        }
        __half* gdst = g_A2 + (size_t)gr * KB_ + ch * 64;
        #pragma unroll
        for (int u = 0; u < 8; ++u)
            *(uint4*)(gdst + u * 8) = *(uint4*)&hv[u * 4];
    }

    CP_WAIT0();
    __syncthreads();

    // ---- MMA: h[32,128] = A @ W1^T over 8 k-chunks
    float acc[2][2][4];
    #pragma unroll
    for (int p = 0; p < 2; ++p)
        #pragma unroll
        for (int j = 0; j < 2; ++j)
            #pragma unroll
            for (int q = 0; q < 4; ++q) acc[p][j][q] = 0.f;

    #pragma unroll
    for (int c = 0; c < 8; ++c) {
        const uint32_t aBase = sbase + c * 4096;
        const uint32_t bBase = sbase + GA_SM + c * 16384;
        const uint32_t rowA = wm * 16 + (lane & 15);
        #pragma unroll
        for (int kk = 0; kk < 4; ++kk) {
            uint32_t a[4];
            uint32_t bcA = kk * 32 + (lane >> 4) * 16;
            LDSM4(a[0], a[1], a[2], a[3], aBase + swz(rowA, bcA));
            #pragma unroll
            for (int p = 0; p < 2; ++p) {
                uint32_t rowB = wn * 32 + p * 16 + ((lane >> 4) & 1) * 8 + (lane & 7);
                uint32_t bcB = kk * 32 + ((lane >> 3) & 1) * 16;
                uint32_t b0, b1, b2, b3;
                LDSM4(b0, b1, b2, b3, bBase + swz(rowB, bcB));
                MMA16816(acc[p][0], a, b0, b1);
                MMA16816(acc[p][1], a, b2, b3);
            }
        }
    }
    __syncthreads();

    // ---- h tile -> smem ----
    float* hs = (float*)gsm;   // [32][132]
    {
        int r0h = wm * 16 + (lane >> 2);
        int cb  = wn * 32 + (lane & 3) * 2;
        #pragma unroll
        for (int p = 0; p < 2; ++p)
            #pragma unroll
            for (int j = 0; j < 2; ++j) {
                int cc = cb + p * 16 + j * 8;
                hs[r0h * 132 + cc]           = acc[p][j][0];
                hs[r0h * 132 + cc + 1]       = acc[p][j][1];
                hs[(r0h + 8) * 132 + cc]     = acc[p][j][2];
                hs[(r0h + 8) * 132 + cc + 1] = acc[p][j][3];
            }
    }
    __syncthreads();

    // ---- GELU + dot(w2) + sigmoid -> scale ----
    float aw = 1.f / (1.f + expf(-alphap[0]));
    #pragma unroll
    for (int rr = 0; rr < 4; ++rr) {
        int r = wid * 4 + rr;
        float s = 0.f;
        #pragma unroll
        for (int q = 0; q < 4; ++q) {
            int cc = lane + 32 * q;
            float x = hs[r * 132 + cc] + b_g1[cc];
            float h = 0.5f * x * (1.f + erff(x * 0.70710678118654752f));
            s += h * W_g2[cc];
        }
        #pragma unroll
        for (int o = 16; o >= 1; o >>= 1) s += __shfl_xor_sync(0xffffffffu, s, o);
        if (lane == 0) {
            float gate = 1.f / (1.f + expf(-(s + b_g2[0])));
            g_scale[m0 + r] = gate * aw + (1.f - aw);
        }
    }
}

// =====================================================================
// K3: main HMMA GEMM C[Mpad,3072] = A@B^T (K=512), scaled epilogue +
//     fused pentachoron partials into g_pp.
// =====================================================================
#define TILE_B    16384
#define STAGE_B2  (2 * TILE_B)
#define NSTAGE    3
#define GEMM_SMEM (NSTAGE * STAGE_B2)    // 98304
#define NS        (KB_ / 64)             // 8

__global__ void __launch_bounds__(256, 2)
k_gemm_mma(float* __restrict__ out, int M)
{
    extern __shared__ char smem[];
    const uint32_t sb = smem_u32(smem);
    const int tid = threadIdx.x, lane = tid & 31;
    const int wid = tid >> 5;
    const int wm = wid & 3, wn = wid >> 2;          // 4 x 2 warp grid
    const int m0 = blockIdx.y * 128;
    const int n0 = blockIdx.x * 128;

    const __half* Ag = g_A2 + (size_t)m0 * KB_;
    const __half* Bg = g_B2 + (size_t)n0 * KB_;

    const int ldRow = tid >> 3, ldCh = (tid & 7) * 8;

    float acc[2][8][4];
    #pragma unroll
    for (int h = 0; h < 2; ++h)
        #pragma unroll
        for (int j = 0; j < 8; ++j)
            #pragma unroll
            for (int q = 0; q < 4; ++q) acc[h][j][q] = 0.f;

    #pragma unroll
    for (int pre = 0; pre < 2; ++pre) {
        uint32_t base = sb + pre * STAGE_B2;
        #pragma unroll
        for (int i = 0; i < 4; ++i) {
            int row = ldRow + i * 32;
            uint32_t doff = swz(row, ldCh * 2);
            CP_ASYNC16(base + doff, (const void*)(Ag + (size_t)row * KB_ + pre * 64 + ldCh));
            CP_ASYNC16(base + TILE_B + doff, (const void*)(Bg + (size_t)row * KB_ + pre * 64 + ldCh));
        }
        CP_COMMIT();
    }

    #pragma unroll 1
    for (int s = 0; s < NS; ++s) {
        CP_WAIT1();
        __syncthreads();
        if (s + 2 < NS) {
            uint32_t base = sb + ((s + 2) % NSTAGE) * STAGE_B2;
            #pragma unroll
            for (int i = 0; i < 4; ++i) {
                int row = ldRow + i * 32;
                uint32_t doff = swz(row, ldCh * 2);
                CP_ASYNC16(base + doff, (const void*)(Ag + (size_t)row * KB_ + (s + 2) * 64 + ldCh));
                CP_ASYNC16(base + TILE_B + doff, (const void*)(Bg + (size_t)row * KB_ + (s + 2) * 64 + ldCh));
            }
        }
        CP_COMMIT();

        const uint32_t stg = sb + (s % NSTAGE) * STAGE_B2;
        const uint32_t rowA0 = wm * 32 + (lane & 15);
        const uint32_t aRB0 = stg + rowA0 * 128, xrA0 = (rowA0 & 7u) << 4;
        const uint32_t aRB1 = aRB0 + 16 * 128;
        #pragma unroll
        for (int kk = 0; kk < 4; ++kk) {
            uint32_t a0[4], a1[4];
            uint32_t bcA = kk * 32 + (lane >> 4) * 16;
            LDSM4(a0[0], a0[1], a0[2], a0[3], aRB0 + (bcA ^ xrA0));
            LDSM4(a1[0], a1[1], a1[2], a1[3], aRB1 + (bcA ^ xrA0));
            #pragma unroll
            for (int p = 0; p < 4; ++p) {
                uint32_t rowB = wn * 64 + p * 16 + ((lane >> 4) & 1) * 8 + (lane & 7);
                uint32_t bcB = kk * 32 + ((lane >> 3) & 1) * 16;
                uint32_t b0, b1, b2, b3;
                LDSM4(b0, b1, b2, b3, stg + TILE_B + swz(rowB, bcB));
                MMA16816(acc[0][2 * p],     a0, b0, b1);
                MMA16816(acc[0][2 * p + 1], a0, b2, b3);
                MMA16816(acc[1][2 * p],     a1, b0, b1);
                MMA16816(acc[1][2 * p + 1], a1, b2, b3);
            }
        }
        __syncthreads();
    }

    // ---- dirs slice into smem ----
    float* ds = (float*)smem;            // [5][128]
    const int ncol0 = n0 & 1023;
    for (int i = tid; i < 640; i += 256) {
        int v = i >> 7, l = i & 127;
        ds[i] = g_dirs[v * EDIM_ + ncol0 + l];
    }
    __syncthreads();

    // ---- epilogue: scale, store, fused proj partials ----
    const int sel  = n0 >> 10;
    const int ncolB = ncol0 + wn * 64;
    const int chunk = blockIdx.x * 2 + wn;          // 0..47
    float* outM = out + (size_t)sel * M * EDIM_;
    #pragma unroll
    for (int h = 0; h < 2; ++h) {
        #pragma unroll
        for (int rr = 0; rr < 2; ++rr) {
            int grow = m0 + wm * 32 + h * 16 + rr * 8 + (lane >> 2);
            float sc = g_scale[grow];
            bool ok = grow < M;
            float* orow = outM + (size_t)grow * EDIM_ + ncolB + 2 * (lane & 3);
            float p0 = 0.f, p1 = 0.f, p2 = 0.f, p3 = 0.f, p4 = 0.f;
            #pragma unroll
            for (int j = 0; j < 8; ++j) {
                float c0 = acc[h][j][2 * rr] * sc;
                float c1 = acc[h][j][2 * rr + 1] * sc;
                if (ok) *(float2*)(orow + j * 8) = make_float2(c0, c1);
                int lc = wn * 64 + j * 8 + 2 * (lane & 3);
                p0 += c0 * ds[lc]       + c1 * ds[lc + 1];
                p1 += c0 * ds[128 + lc] + c1 * ds[128 + lc + 1];
                p2 += c0 * ds[256 + lc] + c1 * ds[256 + lc + 1];
                p3 += c0 * ds[384 + lc] + c1 * ds[384 + lc + 1];
                p4 += c0 * ds[512 + lc] + c1 * ds[512 + lc + 1];
            }
            p0 += __shfl_xor_sync(0xffffffffu, p0, 1); p0 += __shfl_xor_sync(0xffffffffu, p0, 2);
            p1 += __shfl_xor_sync(0xffffffffu, p1, 1); p1 += __shfl_xor_sync(0xffffffffu, p1, 2);
            p2 += __shfl_xor_sync(0xffffffffu, p2, 1); p2 += __shfl_xor_sync(0xffffffffu, p2, 2);
            p3 += __shfl_xor_sync(0xffffffffu, p3, 1); p3 += __shfl_xor_sync(0xffffffffu, p3, 2);
            p4 += __shfl_xor_sync(0xffffffffu, p4, 1); p4 += __shfl_xor_sync(0xffffffffu, p4, 2);
            if (ok && (lane & 3) == 0) {
                g_pp[(0 * 48 + chunk) * MPADMX + grow] = p0;
                g_pp[(1 * 48 + chunk) * MPADMX + grow] = p1;
                g_pp[(2 * 48 + chunk) * MPADMX + grow] = p2;
                g_pp[(3 * 48 + chunk) * MPADMX + grow] = p3;
                g_pp[(4 * 48 + chunk) * MPADMX + grow] = p4;
            }
        }
    }
}

// =====================================================================
// K4: finalize projections: sum 16 chunks per (sel, v, row)
// =====================================================================
__global__ void k_fin(float* __restrict__ out, int N, int M)
{
    int sv = blockIdx.y;            // 0..14
    int sel = sv / 5, v = sv % 5;
    int row = blockIdx.x * 256 + threadIdx.x;
    if (row >= M) return;
    const float* src = g_pp + ((size_t)v * 48 + sel * 16) * MPADMX + row;
    float s = 0.f;
    #pragma unroll
    for (int g = 0; g < 16; ++g) s += src[(size_t)g * MPADMX];
    size_t base = (size_t)3 * M * EDIM_ + (size_t)sel * 5 * M + (size_t)v * M;
    out[base + row] = s;
}

// =====================================================================
extern "C" void kernel_launch(void* const* d_in, const int* in_sizes, int n_in,
                              void* d_out, int out_size)
{
    const float* tokens = (const float*)d_in[0];
    const float* fps    = (const float*)d_in[1];
    const float* W_g1   = (const float*)d_in[2];
    const float* b_g1   = (const float*)d_in[3];
    const float* W_g2   = (const float*)d_in[4];
    const float* b_g2   = (const float*)d_in[5];
    const float* alpha  = (const float*)d_in[6];
    const float* Wq     = (const float*)d_in[7];
    const float* Wk     = (const float*)d_in[8];
    const float* Wv     = (const float*)d_in[9];
    const float* penta  = (const float*)d_in[10];

    int N = out_size / 12348;       // per token: 3*1024 QKV + 3*5 projections
    if (N <= 0) return;
    int M = 4 * N;
    int Mpad = (M + 127) & ~127;
    float* out = (float*)d_out;

    cudaFuncSetAttribute(k_gemm_mma, cudaFuncAttributeMaxDynamicSharedMemorySize, GEMM_SMEM);
    cudaFuncSetAttribute(k_gategather, cudaFuncAttributeMaxDynamicSharedMemorySize, GSMEM);

    k_prep<<<1601, 256>>>(fps, penta, Wq, Wk, Wv, W_g1);
    k_gategather<<<Mpad / 32, 256, GSMEM>>>(tokens, b_g1, W_g2, b_g2, alpha, N, M);
    dim3 g3(24, Mpad / 128);
    k_gemm_mma<<<g3, 256, GEMM_SMEM>>>(out, M);
    dim3 gf((M + 255) / 256, 15);
    k_fin<<<gf, 256>>>(out, N, M);
}